// round 6
// baseline (speedup 1.0000x reference)
#include <cuda_runtime.h>
#include <math.h>

#define H 256
#define G3 768          // 3*H
#define FD 128          // feature dim
#define HEADN 128       // 64 pi + 64 vf columns
#define KC 16           // K-chunk for recurrence GEMM
#define K1C 32          // K-chunk for x-gates GEMM
#define HS_PITCH 36     // skewed pitch for Hs[k][m]

typedef unsigned long long ull;

// ---- packed fp32x2 helpers (Blackwell double-rate fp32; bit-exact FFMA) ----
#define FMA2(acc, a, b) \
    asm volatile("fma.rn.f32x2 %0, %1, %2, %0;" : "+l"(acc) : "l"(a), "l"(b))
#define PACK2(out, lo, hi) \
    asm volatile("mov.b64 %0, {%1, %2};" : "=l"(out) : "f"(lo), "f"(hi))
#define UNPACK2(lo, hi, in) \
    asm volatile("mov.b64 {%0, %1}, %2;" : "=f"(lo), "=f"(hi) : "l"(in))

__device__ __forceinline__ void cp16(void* smem_dst, const void* gsrc) {
    unsigned d = (unsigned)__cvta_generic_to_shared(smem_dst);
    asm volatile("cp.async.cg.shared.global [%0], [%1], 16;" :: "r"(d), "l"(gsrc));
}
#define CP_COMMIT asm volatile("cp.async.commit_group;")
#define CP_WAIT1  asm volatile("cp.async.wait_group 1;")
#define CP_WAIT0  asm volatile("cp.async.wait_group 0;")

// ---------------- scratch (device globals; no allocations allowed) ----------------
__device__ float g_xg[4096UL * 64UL * 768UL];   // [B*T][3H] input gates (+b_ih)
__device__ float g_whhT[H * G3];                // [256][768] w_hh^T (K-major)
__device__ float g_wihT[FD * G3];               // [128][768] w_ih^T (K-major)
__device__ float g_whead[H * HEADN];            // [256][128] [w_pi^T | w_vf^T]

// ---------------- kernel 0: pack / transpose weights ----------------
__global__ void pack_weights(const float* __restrict__ w_ih,
                             const float* __restrict__ w_hh,
                             const float* __restrict__ w_pi,
                             const float* __restrict__ w_vf) {
    int idx = blockIdx.x * blockDim.x + threadIdx.x;
    int stride = gridDim.x * blockDim.x;
    for (int i = idx; i < H * G3; i += stride) {
        int k = i / G3, g = i % G3;
        g_whhT[i] = w_hh[g * H + k];
    }
    for (int i = idx; i < FD * G3; i += stride) {
        int k = i / G3, g = i % G3;
        g_wihT[i] = w_ih[g * FD + k];
    }
    for (int i = idx; i < H * HEADN; i += stride) {
        int k = i / HEADN, j = i % HEADN;
        g_whead[i] = (j < 64) ? w_pi[j * H + k] : w_vf[(j - 64) * H + k];
    }
}

// ---------------- kernel 1: x_gates = features @ w_ih^T + b_ih ----------------
// C tile 64(M) x 128(N), K=128. 256 threads, 8 rows x 4 cols each,
// inner product via FFMA2 on row-pairs (As pair-contiguous in SMEM).
__global__ __launch_bounds__(256) void xgates_gemm(const float* __restrict__ feats,
                                                   const float* __restrict__ b_ih) {
    __shared__ float As[K1C][64];        // As[k][m] (m pair-contiguous for b64 loads)
    __shared__ float Bs[K1C][128];       // Bs[k][n]

    const int t  = threadIdx.x;
    const int tn = t & 31;
    const int tm = t >> 5;               // 0..7
    const int m0 = blockIdx.x * 64;
    const int n0 = blockIdx.y * 128;

    ull acc[4][4];                       // [row-pair][j], each = 2 fp32
#pragma unroll
    for (int i = 0; i < 4; i++)
#pragma unroll
        for (int j = 0; j < 4; j++) acc[i][j] = 0ULL;

    for (int k0 = 0; k0 < FD; k0 += K1C) {
        {   // A chunk: 64 rows x 32 k, transposed into SMEM
            int m  = t >> 2;
            int ks = (t & 3) * 8;
            const float4* src = reinterpret_cast<const float4*>(
                &feats[(size_t)(m0 + m) * FD + k0 + ks]);
            float4 v0 = src[0], v1 = src[1];
            As[ks + 0][m] = v0.x; As[ks + 1][m] = v0.y;
            As[ks + 2][m] = v0.z; As[ks + 3][m] = v0.w;
            As[ks + 4][m] = v1.x; As[ks + 5][m] = v1.y;
            As[ks + 6][m] = v1.z; As[ks + 7][m] = v1.w;
        }
#pragma unroll
        for (int q = 0; q < 4; q++) {    // B chunk from K-major g_wihT
            int f4  = t + 256 * q;
            int row = f4 >> 5;
            int c4  = f4 & 31;
            *reinterpret_cast<float4*>(&Bs[row][c4 * 4]) =
                *reinterpret_cast<const float4*>(
                    &g_wihT[(size_t)(k0 + row) * G3 + n0 + c4 * 4]);
        }
        __syncthreads();

#pragma unroll
        for (int kk = 0; kk < K1C; kk++) {
            const ull* ap = reinterpret_cast<const ull*>(&As[kk][tm * 8]);
            ull a0 = ap[0], a1 = ap[1], a2 = ap[2], a3 = ap[3];
#pragma unroll
            for (int j = 0; j < 4; j++) {
                float w = Bs[kk][tn + 32 * j];
                ull w2; PACK2(w2, w, w);
                FMA2(acc[0][j], a0, w2);
                FMA2(acc[1][j], a1, w2);
                FMA2(acc[2][j], a2, w2);
                FMA2(acc[3][j], a3, w2);
            }
        }
        __syncthreads();
    }

#pragma unroll
    for (int j = 0; j < 4; j++) {
        float b = b_ih[n0 + tn + 32 * j];
#pragma unroll
        for (int ip = 0; ip < 4; ip++) {
            float lo, hi; UNPACK2(lo, hi, acc[ip][j]);
            size_t r0 = (size_t)(m0 + tm * 8 + 2 * ip);
            g_xg[r0 * G3 + n0 + tn + 32 * j]       = lo + b;
            g_xg[(r0 + 1) * G3 + n0 + tn + 32 * j] = hi + b;
        }
    }
}

// ---------------- kernel 2: persistent GRU recurrence + heads ----------------
// Each CTA owns 32 batch rows; h lives in SMEM. Per step: hg = h @ w_hh^T
// (M=32,N=768,K=256) via FFMA2 (weight pairs loaded as b64, h broadcast-packed),
// with the next w_hh chunk prefetched via cp.async double-buffering.
// Lane tn owns gate-column pairs (64p+2tn, 64p+2tn+1), p=0..11
// (p 0-3 -> r, 4-7 -> z, 8-11 -> n, with matching hidden index per p%4).
__global__ __launch_bounds__(256) void gru_recur(const float* __restrict__ b_hh,
                                                 const float* __restrict__ b_pi,
                                                 const float* __restrict__ b_vf,
                                                 float* __restrict__ out,
                                                 int Btot, int Tsteps) {
    extern __shared__ float sm[];
    float* Hs = sm;                       // [256][HS_PITCH]
    float* Ws0 = sm + H * HS_PITCH;       // double buffer [2][KC][768]
    float* Ws1 = Ws0 + KC * G3;

    const int t  = threadIdx.x;
    const int tn = t & 31;
    const int tm = t >> 5;                // 0..7 ; rows tm*4 .. tm*4+3
    const int b0 = blockIdx.x * 32;

    // this thread's slice of a chunk copy: 12 x 16B
    const int ld_row = (t + 0) / 192 * 0; // placeholder (computed in loop)

    for (int i = t; i < H * HS_PITCH; i += 256) Hs[i] = 0.f;
    __syncthreads();

    const int NCH = H / KC;               // 16 chunks per step

    for (int st = 0; st < Tsteps; st++) {
        // prefetch chunk 0 into buffer 0 (overlaps with prior step's epilogue)
#pragma unroll
        for (int q = 0; q < 12; q++) {
            int f4  = t + 256 * q;
            int row = f4 / 192;
            int c4  = f4 % 192;
            cp16(&Ws0[row * G3 + c4 * 4],
                 &g_whhT[(size_t)row * G3 + c4 * 4]);
        }
        CP_COMMIT;

        ull acc[4][12];
#pragma unroll
        for (int i = 0; i < 4; i++)
#pragma unroll
            for (int p = 0; p < 12; p++) acc[i][p] = 0ULL;

        for (int c = 0; c < NCH; c++) {
            float* Wcur = (c & 1) ? Ws1 : Ws0;
            if (c + 1 < NCH) {
                float* Wnxt = ((c + 1) & 1) ? Ws1 : Ws0;
                const int k0n = (c + 1) * KC;
#pragma unroll
                for (int q = 0; q < 12; q++) {
                    int f4  = t + 256 * q;
                    int row = f4 / 192;
                    int c4  = f4 % 192;
                    cp16(&Wnxt[row * G3 + c4 * 4],
                         &g_whhT[(size_t)(k0n + row) * G3 + c4 * 4]);
                }
                CP_COMMIT;
                CP_WAIT1;
            } else {
                CP_WAIT0;
            }
            __syncthreads();

            const int k0 = c * KC;
#pragma unroll
            for (int kk = 0; kk < KC; kk++) {
                float4 av = *reinterpret_cast<const float4*>(
                    &Hs[(k0 + kk) * HS_PITCH + tm * 4]);       // warp broadcast
                ull a2[4];
                PACK2(a2[0], av.x, av.x);
                PACK2(a2[1], av.y, av.y);
                PACK2(a2[2], av.z, av.z);
                PACK2(a2[3], av.w, av.w);
                const ull* wrow = reinterpret_cast<const ull*>(&Wcur[kk * G3]);
#pragma unroll
                for (int p = 0; p < 12; p++) {
                    ull w2 = wrow[p * 32 + tn];                // LDS.64, conflict-free
                    FMA2(acc[0][p], a2[0], w2);
                    FMA2(acc[1][p], a2[1], w2);
                    FMA2(acc[2][p], a2[2], w2);
                    FMA2(acc[3][p], a2[3], w2);
                }
            }
            __syncthreads();
        }

        // gate math + h update (each (i,row) owned by exactly one thread)
#pragma unroll
        for (int p = 0; p < 4; p++) {
            const int i0 = 64 * p + 2 * tn;                    // hidden pair (i0, i0+1)
            const float2 bhr = *reinterpret_cast<const float2*>(&b_hh[i0]);
            const float2 bhz = *reinterpret_cast<const float2*>(&b_hh[H + i0]);
            const float2 bhn = *reinterpret_cast<const float2*>(&b_hh[2 * H + i0]);
#pragma unroll
            for (int ri = 0; ri < 4; ri++) {
                const int row = tm * 4 + ri;
                const size_t gro = ((size_t)(b0 + row) * Tsteps + st) * G3;
                const float2 xr = *reinterpret_cast<const float2*>(&g_xg[gro + i0]);
                const float2 xz = *reinterpret_cast<const float2*>(&g_xg[gro + H + i0]);
                const float2 xn = *reinterpret_cast<const float2*>(&g_xg[gro + 2 * H + i0]);
                float hr0, hr1, hz0, hz1, hn0, hn1;
                UNPACK2(hr0, hr1, acc[ri][p]);
                UNPACK2(hz0, hz1, acc[ri][p + 4]);
                UNPACK2(hn0, hn1, acc[ri][p + 8]);
                {
                    const float r = 1.f / (1.f + __expf(-(xr.x + hr0 + bhr.x)));
                    const float z = 1.f / (1.f + __expf(-(xz.x + hz0 + bhz.x)));
                    const float n = tanhf(xn.x + r * (hn0 + bhn.x));
                    const float hold = Hs[i0 * HS_PITCH + row];
                    Hs[i0 * HS_PITCH + row] = (1.f - z) * n + z * hold;
                }
                {
                    const float r = 1.f / (1.f + __expf(-(xr.y + hr1 + bhr.y)));
                    const float z = 1.f / (1.f + __expf(-(xz.y + hz1 + bhz.y)));
                    const float n = tanhf(xn.y + r * (hn1 + bhn.y));
                    const float hold = Hs[(i0 + 1) * HS_PITCH + row];
                    Hs[(i0 + 1) * HS_PITCH + row] = (1.f - z) * n + z * hold;
                }
            }
        }
        __syncthreads();
    }

    // LeakyReLU on final h (in place; same ownership as epilogue)
#pragma unroll
    for (int p = 0; p < 4; p++) {
        const int i0 = 64 * p + 2 * tn;
#pragma unroll
        for (int ri = 0; ri < 4; ri++) {
            const int row = tm * 4 + ri;
            float v0 = Hs[i0 * HS_PITCH + row];
            float v1 = Hs[(i0 + 1) * HS_PITCH + row];
            Hs[i0 * HS_PITCH + row]       = (v0 >= 0.f) ? v0 : 0.01f * v0;
            Hs[(i0 + 1) * HS_PITCH + row] = (v1 >= 0.f) ? v1 : 0.01f * v1;
        }
    }
    __syncthreads();

    // heads: [32,256] @ [256,128] (pi cols 0..63, vf cols 64..127), reuse Ws0
    float acc2[4][4];
#pragma unroll
    for (int i = 0; i < 4; i++)
#pragma unroll
        for (int j = 0; j < 4; j++) acc2[i][j] = 0.f;

    for (int k0 = 0; k0 < H; k0 += KC) {
#pragma unroll
        for (int q = 0; q < 2; q++) {
            int f4  = t + 256 * q;
            int row = f4 >> 5;
            int c4  = f4 & 31;
            *reinterpret_cast<float4*>(&Ws0[row * HEADN + c4 * 4]) =
                *reinterpret_cast<const float4*>(
                    &g_whead[(size_t)(k0 + row) * HEADN + c4 * 4]);
        }
        __syncthreads();
#pragma unroll
        for (int kk = 0; kk < KC; kk++) {
            float4 av = *reinterpret_cast<const float4*>(
                &Hs[(k0 + kk) * HS_PITCH + tm * 4]);
            float a[4] = {av.x, av.y, av.z, av.w};
#pragma unroll
            for (int j = 0; j < 4; j++) {
                float w = Ws0[kk * HEADN + tn + 32 * j];
#pragma unroll
                for (int i = 0; i < 4; i++)
                    acc2[i][j] = fmaf(a[i], w, acc2[i][j]);
            }
        }
        __syncthreads();
    }

#pragma unroll
    for (int j = 0; j < 4; j++) {
        const int c = tn + 32 * j;
        const float bias = (c < 64) ? b_pi[c] : b_vf[c - 64];
#pragma unroll
        for (int ri = 0; ri < 4; ri++) {
            const int row = tm * 4 + ri;
            float y = acc2[ri][j] + bias;
            y = (y >= 0.f) ? y : 0.01f * y;
            size_t o = (c < 64)
                ? ((size_t)(b0 + row) * 64 + c)
                : ((size_t)Btot * 64 + (size_t)(b0 + row) * 64 + (c - 64));
            out[o] = y;
        }
    }
}

// ---------------- launch ----------------
extern "C" void kernel_launch(void* const* d_in, const int* in_sizes, int n_in,
                              void* d_out, int out_size) {
    const float* feats = (const float*)d_in[0];
    const float* w_ih  = (const float*)d_in[1];
    const float* w_hh  = (const float*)d_in[2];
    const float* b_ih  = (const float*)d_in[3];
    const float* b_hh  = (const float*)d_in[4];
    const float* w_pi  = (const float*)d_in[5];
    const float* b_pi  = (const float*)d_in[6];
    const float* w_vf  = (const float*)d_in[7];
    const float* b_vf  = (const float*)d_in[8];
    float* out = (float*)d_out;

    const int Btot   = out_size / 128;              // out = 2 * B * 64
    const int Tsteps = in_sizes[0] / (Btot * FD);
    const int rows   = Btot * Tsteps;

    const size_t smem2 = (size_t)(H * HS_PITCH + 2 * KC * G3) * sizeof(float); // ~132 KB
    cudaFuncSetAttribute(gru_recur, cudaFuncAttributeMaxDynamicSharedMemorySize,
                         (int)smem2);

    pack_weights<<<64, 256>>>(w_ih, w_hh, w_pi, w_vf);
    xgates_gemm<<<dim3(rows / 64, G3 / 128), 256>>>(feats, b_ih);
    gru_recur<<<Btot / 32, 256, smem2>>>(b_hh, b_pi, b_vf, out, Btot, Tsteps);
}

// round 8
// speedup vs baseline: 1.2016x; 1.2016x over previous
#include <cuda_runtime.h>
#include <math.h>
#include <stdint.h>

#define H 256
#define G3 768
#define FD 128
#define HEADN 128
#define KC 16
#define HS_PITCH 36
#define XP 132            // padded SMEM pitch for mma fragment tiles

typedef unsigned long long ull;

// ---- packed fp32x2 (bit-exact double-rate FFMA) ----
#define FMA2(acc, a, b) \
    asm volatile("fma.rn.f32x2 %0, %1, %2, %0;" : "+l"(acc) : "l"(a), "l"(b))
#define PACK2(out, lo, hi) \
    asm volatile("mov.b64 %0, {%1, %2};" : "=l"(out) : "f"(lo), "f"(hi))
#define UNPACK2(lo, hi, in) \
    asm volatile("mov.b64 {%0, %1}, %2;" : "=f"(lo), "=f"(hi) : "l"(in))

__device__ __forceinline__ void cp16(void* smem_dst, const void* gsrc) {
    unsigned d = (unsigned)__cvta_generic_to_shared(smem_dst);
    asm volatile("cp.async.cg.shared.global [%0], [%1], 16;" :: "r"(d), "l"(gsrc));
}
#define CP_COMMIT asm volatile("cp.async.commit_group;")
#define CP_WAIT1  asm volatile("cp.async.wait_group 1;")
#define CP_WAIT0  asm volatile("cp.async.wait_group 0;")

__device__ __forceinline__ uint32_t f2tf32(float f) {
    uint32_t o;
    asm("cvt.rna.tf32.f32 %0, %1;" : "=r"(o) : "f"(f));
    return o;
}

// mma.sync m16n8k8 tf32 (A row-major, B col-major), acc in-place
#define MMA_TF32(c, a, b) \
    asm volatile("mma.sync.aligned.m16n8k8.row.col.f32.tf32.tf32.f32 " \
        "{%0,%1,%2,%3}, {%4,%5,%6,%7}, {%8,%9}, {%0,%1,%2,%3};" \
        : "+f"((c)[0]), "+f"((c)[1]), "+f"((c)[2]), "+f"((c)[3]) \
        : "r"((a)[0]), "r"((a)[1]), "r"((a)[2]), "r"((a)[3]), \
          "r"((b)[0]), "r"((b)[1]))

// ---------------- scratch ----------------
__device__ float g_xg[4096UL * 64UL * 768UL];
__device__ float g_whhT[H * G3];
__device__ float g_whead[H * HEADN];

// ---------------- kernel 0: pack ----------------
__global__ void pack_weights(const float* __restrict__ w_hh,
                             const float* __restrict__ w_pi,
                             const float* __restrict__ w_vf) {
    int idx = blockIdx.x * blockDim.x + threadIdx.x;
    int stride = gridDim.x * blockDim.x;
    for (int i = idx; i < H * G3; i += stride) {
        int k = i / G3, g = i % G3;
        g_whhT[i] = w_hh[g * H + k];
    }
    for (int i = idx; i < H * HEADN; i += stride) {
        int k = i / HEADN, j = i % HEADN;
        g_whead[i] = (j < 64) ? w_pi[j * H + k] : w_vf[(j - 64) * H + k];
    }
}

// ---------------- kernel 1: x_gates via mma.sync tf32 ----------------
// CTA tile 128(M) x 128(N), K=128 resident. 8 warps in 2(M) x 4(N); warp tile
// 64x32 = 4x4 m16n8k8 tiles. Operands tf32-rounded during the SMEM fill.
// Padded pitch XP=132 makes all fragment LDS conflict-free (bank = lane).
__global__ __launch_bounds__(256, 1) void xgates_mma_sync(const float* __restrict__ feats,
                                                          const float* __restrict__ w_ih,
                                                          const float* __restrict__ b_ih) {
    extern __shared__ uint32_t xs[];
    uint32_t* As = xs;                 // [128][XP]
    uint32_t* Bs = xs + 128 * XP;      // [128][XP]

    const int t = threadIdx.x;
    const int lane = t & 31;
    const int w = t >> 5;
    const int wm = w & 1;              // 0..1
    const int wn = w >> 1;             // 0..3
    const int m0 = blockIdx.x * 128;
    const int n0 = blockIdx.y * 128;

    // fill A (feats tile) and B (w_ih rows n0..n0+127), cvt to tf32
#pragma unroll
    for (int q = 0; q < 16; q++) {
        int idx = t + 256 * q, row = idx >> 5, c4 = idx & 31;
        float4 va = *reinterpret_cast<const float4*>(
            &feats[(size_t)(m0 + row) * FD + c4 * 4]);
        uint4 ua = {f2tf32(va.x), f2tf32(va.y), f2tf32(va.z), f2tf32(va.w)};
        *reinterpret_cast<uint4*>(&As[row * XP + c4 * 4]) = ua;
        float4 vb = *reinterpret_cast<const float4*>(
            &w_ih[(size_t)(n0 + row) * FD + c4 * 4]);
        uint4 ub = {f2tf32(vb.x), f2tf32(vb.y), f2tf32(vb.z), f2tf32(vb.w)};
        *reinterpret_cast<uint4*>(&Bs[row * XP + c4 * 4]) = ub;
    }
    __syncthreads();

    float acc[16][4];
#pragma unroll
    for (int i = 0; i < 16; i++)
#pragma unroll
        for (int j = 0; j < 4; j++) acc[i][j] = 0.f;

    const int rA = wm * 64 + (lane >> 2);    // A fragment base row
    const int rB = wn * 32 + (lane >> 2);    // B fragment base row (n)
    const int kl = lane & 3;

#pragma unroll
    for (int ks = 0; ks < 16; ks++) {
        const int k0 = ks * 8 + kl;
        uint32_t a[4][4], b[4][2];
#pragma unroll
        for (int mt = 0; mt < 4; mt++) {
            const int r = rA + mt * 16;
            a[mt][0] = As[r * XP + k0];
            a[mt][1] = As[(r + 8) * XP + k0];
            a[mt][2] = As[r * XP + k0 + 4];
            a[mt][3] = As[(r + 8) * XP + k0 + 4];
        }
#pragma unroll
        for (int nt = 0; nt < 4; nt++) {
            const int n = rB + nt * 8;
            b[nt][0] = Bs[n * XP + k0];
            b[nt][1] = Bs[n * XP + k0 + 4];
        }
#pragma unroll
        for (int mt = 0; mt < 4; mt++)
#pragma unroll
            for (int nt = 0; nt < 4; nt++)
                MMA_TF32(acc[mt * 4 + nt], a[mt], b[nt]);
    }

    // epilogue: + b_ih, store float2 pairs
#pragma unroll
    for (int nt = 0; nt < 4; nt++) {
        const int col = n0 + wn * 32 + nt * 8 + 2 * kl;
        const float bx = b_ih[col], by = b_ih[col + 1];
#pragma unroll
        for (int mt = 0; mt < 4; mt++) {
            const int r = m0 + wm * 64 + mt * 16 + (lane >> 2);
            float2 v0 = {acc[mt * 4 + nt][0] + bx, acc[mt * 4 + nt][1] + by};
            float2 v1 = {acc[mt * 4 + nt][2] + bx, acc[mt * 4 + nt][3] + by};
            *reinterpret_cast<float2*>(&g_xg[(size_t)r * G3 + col]) = v0;
            *reinterpret_cast<float2*>(&g_xg[(size_t)(r + 8) * G3 + col]) = v1;
        }
    }
}

// ---------------- kernel 2: persistent GRU recurrence + heads ----------------
// CTA owns 32 batch rows; h in SMEM. Lane tn owns col quads 128q+4tn (q=0..5):
// q0,1 = r gate, q2,3 = z, q4,5 = n. Weights read as LDS.128.
__global__ __launch_bounds__(256) void gru_recur(const float* __restrict__ b_hh,
                                                 const float* __restrict__ b_pi,
                                                 const float* __restrict__ b_vf,
                                                 float* __restrict__ out,
                                                 int Btot, int Tsteps) {
    extern __shared__ float sm[];
    float* Hs = sm;                       // [256][HS_PITCH]
    float* Ws0 = sm + H * HS_PITCH;       // [2][KC][768]
    float* Ws1 = Ws0 + KC * G3;

    const int t  = threadIdx.x;
    const int tn = t & 31;
    const int tm = t >> 5;
    const int b0 = blockIdx.x * 32;

    for (int i = t; i < H * HS_PITCH; i += 256) Hs[i] = 0.f;
    __syncthreads();

    const int NCH = H / KC;

    for (int st = 0; st < Tsteps; st++) {
#pragma unroll
        for (int q = 0; q < 12; q++) {
            int f4 = t + 256 * q, row = f4 / 192, c4 = f4 % 192;
            cp16(&Ws0[row * G3 + c4 * 4], &g_whhT[(size_t)row * G3 + c4 * 4]);
        }
        CP_COMMIT;

        ull acc[4][12];
#pragma unroll
        for (int i = 0; i < 4; i++)
#pragma unroll
            for (int p = 0; p < 12; p++) acc[i][p] = 0ULL;

        for (int c = 0; c < NCH; c++) {
            float* Wcur = (c & 1) ? Ws1 : Ws0;
            if (c + 1 < NCH) {
                float* Wnxt = ((c + 1) & 1) ? Ws1 : Ws0;
                const int k0n = (c + 1) * KC;
#pragma unroll
                for (int q = 0; q < 12; q++) {
                    int f4 = t + 256 * q, row = f4 / 192, c4 = f4 % 192;
                    cp16(&Wnxt[row * G3 + c4 * 4], &g_whhT[(size_t)(k0n + row) * G3 + c4 * 4]);
                }
                CP_COMMIT;
                CP_WAIT1;
            } else {
                CP_WAIT0;
            }
            __syncthreads();

            const int k0 = c * KC;
#pragma unroll
            for (int kk = 0; kk < KC; kk++) {
                float4 av = *reinterpret_cast<const float4*>(&Hs[(k0 + kk) * HS_PITCH + tm * 4]);
                ull a2[4];
                PACK2(a2[0], av.x, av.x);
                PACK2(a2[1], av.y, av.y);
                PACK2(a2[2], av.z, av.z);
                PACK2(a2[3], av.w, av.w);
                const ulonglong2* wrow = reinterpret_cast<const ulonglong2*>(&Wcur[kk * G3]);
#pragma unroll
                for (int q = 0; q < 6; q++) {
                    ulonglong2 w2 = wrow[q * 32 + tn];      // LDS.128, conflict-free
#pragma unroll
                    for (int i = 0; i < 4; i++) {
                        FMA2(acc[i][2 * q],     a2[i], w2.x);
                        FMA2(acc[i][2 * q + 1], a2[i], w2.y);
                    }
                }
            }
            __syncthreads();
        }

        // gate math + h update
#pragma unroll
        for (int qq = 0; qq < 2; qq++) {
            const int i0 = 128 * qq + 4 * tn;
            const float4 bhr = *reinterpret_cast<const float4*>(&b_hh[i0]);
            const float4 bhz = *reinterpret_cast<const float4*>(&b_hh[H + i0]);
            const float4 bhn = *reinterpret_cast<const float4*>(&b_hh[2 * H + i0]);
            const float bhrv[4] = {bhr.x, bhr.y, bhr.z, bhr.w};
            const float bhzv[4] = {bhz.x, bhz.y, bhz.z, bhz.w};
            const float bhnv[4] = {bhn.x, bhn.y, bhn.z, bhn.w};
#pragma unroll
            for (int ri = 0; ri < 4; ri++) {
                const int row = tm * 4 + ri;
                const size_t gro = ((size_t)(b0 + row) * Tsteps + st) * G3;
                const float4 xr = *reinterpret_cast<const float4*>(&g_xg[gro + i0]);
                const float4 xz = *reinterpret_cast<const float4*>(&g_xg[gro + H + i0]);
                const float4 xn = *reinterpret_cast<const float4*>(&g_xg[gro + 2 * H + i0]);
                const float xrv[4] = {xr.x, xr.y, xr.z, xr.w};
                const float xzv[4] = {xz.x, xz.y, xz.z, xz.w};
                const float xnv[4] = {xn.x, xn.y, xn.z, xn.w};
                float hr[4], hz[4], hn[4];
                UNPACK2(hr[0], hr[1], acc[ri][2 * qq + 0]);
                UNPACK2(hr[2], hr[3], acc[ri][2 * qq + 1]);
                UNPACK2(hz[0], hz[1], acc[ri][4 + 2 * qq]);
                UNPACK2(hz[2], hz[3], acc[ri][5 + 2 * qq]);
                UNPACK2(hn[0], hn[1], acc[ri][8 + 2 * qq]);
                UNPACK2(hn[2], hn[3], acc[ri][9 + 2 * qq]);
#pragma unroll
                for (int e = 0; e < 4; e++) {
                    const float r = 1.f / (1.f + __expf(-(xrv[e] + hr[e] + bhrv[e])));
                    const float z = 1.f / (1.f + __expf(-(xzv[e] + hz[e] + bhzv[e])));
                    const float n = tanhf(xnv[e] + r * (hn[e] + bhnv[e]));
                    const float hold = Hs[(i0 + e) * HS_PITCH + row];
                    Hs[(i0 + e) * HS_PITCH + row] = (1.f - z) * n + z * hold;
                }
            }
        }
        __syncthreads();
    }

    // LeakyReLU on final h
#pragma unroll
    for (int qq = 0; qq < 2; qq++) {
        const int i0 = 128 * qq + 4 * tn;
#pragma unroll
        for (int ri = 0; ri < 4; ri++) {
            const int row = tm * 4 + ri;
#pragma unroll
            for (int e = 0; e < 4; e++) {
                float v = Hs[(i0 + e) * HS_PITCH + row];
                Hs[(i0 + e) * HS_PITCH + row] = (v >= 0.f) ? v : 0.01f * v;
            }
        }
    }
    __syncthreads();

    // heads: [32,256] @ [256,128]
    float acc2[4][4];
#pragma unroll
    for (int i = 0; i < 4; i++)
#pragma unroll
        for (int j = 0; j < 4; j++) acc2[i][j] = 0.f;

    for (int k0 = 0; k0 < H; k0 += KC) {
#pragma unroll
        for (int q = 0; q < 2; q++) {
            int f4 = t + 256 * q, row = f4 >> 5, c4 = f4 & 31;
            *reinterpret_cast<float4*>(&Ws0[row * HEADN + c4 * 4]) =
                *reinterpret_cast<const float4*>(&g_whead[(size_t)(k0 + row) * HEADN + c4 * 4]);
        }
        __syncthreads();
#pragma unroll
        for (int kk = 0; kk < KC; kk++) {
            float4 av = *reinterpret_cast<const float4*>(&Hs[(k0 + kk) * HS_PITCH + tm * 4]);
            float a[4] = {av.x, av.y, av.z, av.w};
#pragma unroll
            for (int j = 0; j < 4; j++) {
                float w = Ws0[kk * HEADN + tn + 32 * j];
#pragma unroll
                for (int i = 0; i < 4; i++)
                    acc2[i][j] = fmaf(a[i], w, acc2[i][j]);
            }
        }
        __syncthreads();
    }

#pragma unroll
    for (int j = 0; j < 4; j++) {
        const int c = tn + 32 * j;
        const float bias = (c < 64) ? b_pi[c] : b_vf[c - 64];
#pragma unroll
        for (int ri = 0; ri < 4; ri++) {
            const int row = tm * 4 + ri;
            float y = acc2[ri][j] + bias;
            y = (y >= 0.f) ? y : 0.01f * y;
            size_t o = (c < 64)
                ? ((size_t)(b0 + row) * 64 + c)
                : ((size_t)Btot * 64 + (size_t)(b0 + row) * 64 + (c - 64));
            out[o] = y;
        }
    }
}

// ---------------- launch ----------------
extern "C" void kernel_launch(void* const* d_in, const int* in_sizes, int n_in,
                              void* d_out, int out_size) {
    const float* feats = (const float*)d_in[0];
    const float* w_ih  = (const float*)d_in[1];
    const float* w_hh  = (const float*)d_in[2];
    const float* b_ih  = (const float*)d_in[3];
    const float* b_hh  = (const float*)d_in[4];
    const float* w_pi  = (const float*)d_in[5];
    const float* b_pi  = (const float*)d_in[6];
    const float* w_vf  = (const float*)d_in[7];
    const float* b_vf  = (const float*)d_in[8];
    float* out = (float*)d_out;

    const int Btot   = out_size / 128;
    const int Tsteps = in_sizes[0] / (Btot * FD);
    const int rows   = Btot * Tsteps;

    const size_t smem2 = (size_t)(H * HS_PITCH + 2 * KC * G3) * sizeof(float); // ~132 KB
    const size_t smemX = (size_t)(2 * 128 * XP) * sizeof(uint32_t);            // ~132 KB
    cudaFuncSetAttribute(gru_recur, cudaFuncAttributeMaxDynamicSharedMemorySize, (int)smem2);
    cudaFuncSetAttribute(xgates_mma_sync, cudaFuncAttributeMaxDynamicSharedMemorySize, (int)smemX);

    pack_weights<<<64, 256>>>(w_hh, w_pi, w_vf);
    xgates_mma_sync<<<dim3(rows / 128, G3 / 128), 256, smemX>>>(feats, w_ih, b_ih);
    gru_recur<<<Btot / 32, 256, smem2>>>(b_hh, b_pi, b_vf, out, Btot, Tsteps);
}